// round 11
// baseline (speedup 1.0000x reference)
#include <cuda_runtime.h>
#include <cuda_bf16.h>
#include <cstdint>

#define TT 256
#define BB 64
#define DD 1024
#define HH 1024
#define G4 4096
#define EPSF 0.01f
#define NCTA 128
#define NTHR 512

typedef unsigned long long ull;
typedef unsigned short u16;

// ---------------- device scratch -------------------------------------------
static __device__ float g_G[(size_t)TT * BB * G4];   // x@W_ih.T + b_ih + b_hh
static __device__ float g_xn2[TT * BB];              // |x_t|^2
static __device__ float g_hn2[(TT + 1) * BB];        // |h_t|^2 (atomics)
// A-image in mma fragment layout: [parity][kt(64)*mt(8)*lane(32)] uint4
static __device__ uint4 g_Ahi[2][16384];
static __device__ uint4 g_Alo[2][16384];
static __device__ unsigned g_bar;

// ---------------- init (runs every replay) ----------------------------------
__global__ void init_kernel() {
    int idx = blockIdx.x * blockDim.x + threadIdx.x;
    int stride = gridDim.x * blockDim.x;
    uint4 z = make_uint4(0u, 0u, 0u, 0u);
    for (int i = idx; i < 16384; i += stride) {
        g_Ahi[0][i] = z;
        g_Alo[0][i] = z;
    }
    for (int i = idx; i < (TT + 1) * BB; i += stride) g_hn2[i] = 0.f;
    if (idx == 0) g_bar = 0u;
}

// ---------------- |x_t|^2 ---------------------------------------------------
__global__ void xnorm_kernel(const float* __restrict__ x) {
    int row = blockIdx.x;
    const float* xr = x + (size_t)row * DD;
    float s = 0.f;
    for (int i = threadIdx.x; i < DD; i += blockDim.x) { float v = xr[i]; s += v * v; }
    __shared__ float red[8];
    #pragma unroll
    for (int o = 16; o > 0; o >>= 1) s += __shfl_xor_sync(0xffffffffu, s, o);
    if ((threadIdx.x & 31) == 0) red[threadIdx.x >> 5] = s;
    __syncthreads();
    if (threadIdx.x < 8) {
        s = red[threadIdx.x];
        #pragma unroll
        for (int o = 4; o > 0; o >>= 1) s += __shfl_xor_sync(0xffu, s, o);
        if (threadIdx.x == 0) g_xn2[row] = s;
    }
}

// ---------------- mma helpers -------------------------------------------------
__device__ __forceinline__ void mma_bf16(float* d, uint4 a, uint32_t b0, uint32_t b1) {
    asm volatile(
        "mma.sync.aligned.m16n8k16.row.col.f32.bf16.bf16.f32 "
        "{%0,%1,%2,%3}, {%4,%5,%6,%7}, {%8,%9}, {%0,%1,%2,%3};"
        : "+f"(d[0]), "+f"(d[1]), "+f"(d[2]), "+f"(d[3])
        : "r"(a.x), "r"(a.y), "r"(a.z), "r"(a.w), "r"(b0), "r"(b1));
}
__device__ __forceinline__ u16 bfu(__nv_bfloat16 b) {
    return __bfloat16_as_ushort(b);
}
__device__ __forceinline__ void split_bf(float v, u16& h, u16& l) {
    __nv_bfloat16 hb = __float2bfloat16(v);
    h = bfu(hb);
    l = bfu(__float2bfloat16(v - __bfloat162float(hb)));
}
#define CP16(dst, src) \
    asm volatile("cp.async.cg.shared.global [%0], [%1], 16;" \
                 :: "r"(dst), "l"(src) : "memory")
#define CP_COMMIT() asm volatile("cp.async.commit_group;" ::: "memory")
#define CP_WAIT(n)  asm volatile("cp.async.wait_group %0;" :: "n"(n) : "memory")

// ---------------- HMMA precompute GEMM: G = x @ W_ih.T + (b_ih + b_hh) ------
#define PG_XF_BYTES 32768
#define PG_SMEM     65536

__global__ void __launch_bounds__(256)
pre_gemm_hmma(const float* __restrict__ x, const float* __restrict__ Wih,
              const float* __restrict__ bih, const float* __restrict__ bhh) {
    extern __shared__ __align__(16) char sraw[];
    u16*   xf16 = (u16*)sraw;
    u16*   wf16 = (u16*)(sraw + PG_XF_BYTES);
    uint4* xfv  = (uint4*)sraw;
    uint4* wfv  = (uint4*)(sraw + PG_XF_BYTES);

    const int tid  = threadIdx.x;
    const int w    = tid >> 5;
    const int lane = tid & 31;
    const int gid  = lane >> 2;
    const int tig  = lane & 3;
    const int wm   = w >> 1;
    const int wn   = w & 1;
    const int n0   = blockIdx.x * 128;
    const int m0   = blockIdx.y * 128;
    const int lr   = tid >> 4;
    const int lkp  = tid & 15;

    float acc[2][8][4];
    #pragma unroll
    for (int i = 0; i < 2; i++)
        #pragma unroll
        for (int j = 0; j < 8; j++)
            #pragma unroll
            for (int e = 0; e < 4; e++) acc[i][j][e] = 0.f;

    float2 xs[8], ws[8];
    auto LDG_CHUNK = [&](int k0) {
        #pragma unroll
        for (int i = 0; i < 8; i++) {
            int r = lr + i * 16;
            xs[i] = __ldg((const float2*)(x   + (size_t)(m0 + r) * DD + k0 + lkp * 2));
            ws[i] = __ldg((const float2*)(Wih + (size_t)(n0 + r) * DD + k0 + lkp * 2));
        }
    };
    auto STS_CHUNK = [&](int buf) {
        const int kt   = lkp >> 3;
        const int tigc = lkp & 3;
        const int regk = (lkp >> 2) & 1;
        #pragma unroll
        for (int i = 0; i < 8; i++) {
            int r = lr + i * 16;
            u16 h0, l0, h1, l1;
            split_bf(xs[i].x, h0, l0);
            split_bf(xs[i].y, h1, l1);
            int fi = kt * 8 + (r >> 4);
            int lane_f = (r & 7) * 4 + tigc;
            int reg = ((r >> 3) & 1) + 2 * regk;
            int base = ((buf * 16 + fi) * 32 + lane_f) * 16 + reg * 2;
            *(ushort2*)&xf16[base]     = make_ushort2(h0, h1);
            *(ushort2*)&xf16[base + 8] = make_ushort2(l0, l1);

            split_bf(ws[i].x, h0, l0);
            split_bf(ws[i].y, h1, l1);
            int wi = kt * 16 + (r >> 3);
            int wbase = ((buf * 32 + wi) * 32 + lane_f) * 8 + regk * 2;
            *(ushort2*)&wf16[wbase]     = make_ushort2(h0, h1);
            *(ushort2*)&wf16[wbase + 4] = make_ushort2(l0, l1);
        }
    };

    LDG_CHUNK(0);
    STS_CHUNK(0);
    __syncthreads();

    for (int ch = 0; ch < 32; ch++) {
        const int buf = ch & 1;
        if (ch < 31) LDG_CHUNK((ch + 1) * 32);
        #pragma unroll
        for (int kt = 0; kt < 2; kt++) {
            int fi0 = (buf * 16 + kt * 8 + wm * 2) * 32 + lane;
            uint4 ah0 = xfv[fi0 * 2],        al0 = xfv[fi0 * 2 + 1];
            uint4 ah1 = xfv[(fi0 + 32) * 2], al1 = xfv[(fi0 + 32) * 2 + 1];
            #pragma unroll
            for (int nf = 0; nf < 8; nf++) {
                uint4 wv = wfv[(buf * 32 + kt * 16 + wn * 8 + nf) * 32 + lane];
                mma_bf16(acc[0][nf], ah0, wv.x, wv.y);
                mma_bf16(acc[0][nf], al0, wv.x, wv.y);
                mma_bf16(acc[0][nf], ah0, wv.z, wv.w);
                mma_bf16(acc[1][nf], ah1, wv.x, wv.y);
                mma_bf16(acc[1][nf], al1, wv.x, wv.y);
                mma_bf16(acc[1][nf], ah1, wv.z, wv.w);
            }
        }
        if (ch < 31) {
            __syncthreads();
            STS_CHUNK(buf ^ 1);
            __syncthreads();
        }
    }

    #pragma unroll
    for (int nf = 0; nf < 8; nf++) {
        int col = n0 + wn * 64 + nf * 8 + tig * 2;
        float bs0 = __ldg(&bih[col])     + __ldg(&bhh[col]);
        float bs1 = __ldg(&bih[col + 1]) + __ldg(&bhh[col + 1]);
        #pragma unroll
        for (int im = 0; im < 2; im++) {
            int row = m0 + wm * 32 + im * 16 + gid;
            float2 v0; v0.x = acc[im][nf][0] + bs0; v0.y = acc[im][nf][1] + bs1;
            float2 v1; v1.x = acc[im][nf][2] + bs0; v1.y = acc[im][nf][3] + bs1;
            *(float2*)&g_G[(size_t)row * G4 + col]       = v0;
            *(float2*)&g_G[(size_t)(row + 8) * G4 + col] = v1;
        }
    }
}

// ---------------- persistent HMMA recurrence kernel ---------------------------
// 16 warps; warp = (mt = w&7, kh = w>>3). A fragments streamed via cp.async
// into a warp-private SMEM ring (4 slots, 3 in flight) -> zero LDG scoreboard
// stalls, zero prefetch registers. Split accumulators (8 HMMA chains/warp).
// SMEM: Wfrag uint4[64 kt][4 q][32 lane] = 128KB;
//       ring  uint4[16 w][4 slot][32 lane][2] = 64KB
//       pre float[2 kh][128][34] = 34816B, OVERLAYS ring after mainloop.
#define WFRAG_BYTES (256 * 32 * 16)
#define RING_BYTES  65536
#define PRE_STRIDE 34
#define PRE_HALF   (128 * PRE_STRIDE)
#define SMEM_TOTAL (WFRAG_BYTES + RING_BYTES)

__global__ void __launch_bounds__(NTHR, 1)
persist_kernel(const float* __restrict__ gp, const float* __restrict__ Whh,
               float* __restrict__ out) {
    extern __shared__ __align__(16) char sraw[];
    uint4* Wfrag = (uint4*)sraw;
    float* pre   = (float*)(sraw + WFRAG_BYTES);   // overlays ring post-GEMM

    const int tid  = threadIdx.x;
    const int w    = tid >> 5;
    const int lane = tid & 31;
    const int mt   = w & 7;
    const int kh   = w >> 3;
    const int gid  = lane >> 2;
    const int tig  = lane & 3;
    const int n0   = blockIdx.x * 8;
    const int jj   = tid & 7;
    const int b    = tid >> 3;           // 0..63 (tid < 512)

    // warp-private ring: slot stride 1KB, per-lane 32B (hi uint4, lo uint4)
    const uint32_t ring_sm =
        (uint32_t)__cvta_generic_to_shared(sraw + WFRAG_BYTES) + w * 4096 + lane * 32;
    const uint4* ring_rd = (const uint4*)(sraw + WFRAG_BYTES + w * 4096 + lane * 32);

    // ---- one-time: build W fragments (hi/lo) into SMEM ----------------------
    #pragma unroll 1
    for (int idx = w; idx < 256; idx += 16) {
        int q = idx & 3, kt = idx >> 2;
        const float* wr = Whh + (size_t)(q * HH + n0 + gid) * HH + kt * 16 + tig * 2;
        float v00 = __ldg(wr), v01 = __ldg(wr + 1);
        float v10 = __ldg(wr + 8), v11 = __ldg(wr + 9);
        u16 h00, l00, h01, l01, h10, l10, h11, l11;
        split_bf(v00, h00, l00); split_bf(v01, h01, l01);
        split_bf(v10, h10, l10); split_bf(v11, h11, l11);
        Wfrag[idx * 32 + lane] = make_uint4(
            (uint32_t)h00 | ((uint32_t)h01 << 16),
            (uint32_t)h10 | ((uint32_t)h11 << 16),
            (uint32_t)l00 | ((uint32_t)l01 << 16),
            (uint32_t)l10 | ((uint32_t)l11 << 16));
    }
    __syncthreads();

    float cst = 0.f, dcst = 0.f;
    const size_t OFF = (size_t)TT * BB * HH;

    for (int t = 0; t < TT; t++) {
        // ---- prefetch elementwise operands ----------------------------------
        float Gr[4], Pr[4], xnv, hnv;
        {
            size_t gb = ((size_t)t * BB + b) * G4 + n0 + jj;
            #pragma unroll
            for (int q = 0; q < 4; q++) {
                Gr[q] = __ldg(&g_G[gb + q * HH]);
                Pr[q] = EPSF * __ldg(&gp[gb + q * HH]);
            }
            xnv = __ldg(&g_xn2[t * BB + b]);
            hnv = __ldcg(&g_hn2[t * BB + b]);
        }

        // ---- HMMA mainloop with cp.async A-ring -------------------------------
        float acc_a[4][4], acc_b[4][4];
        #pragma unroll
        for (int q = 0; q < 4; q++)
            #pragma unroll
            for (int e = 0; e < 4; e++) { acc_a[q][e] = 0.f; acc_b[q][e] = 0.f; }

        const uint4* Ah = g_Ahi[t & 1];
        const uint4* Al = g_Alo[t & 1];
        const int ktb   = kh * 32;
        const int fbase = mt * 32 + lane;

        // prologue: 3 groups in flight
        #pragma unroll
        for (int d = 0; d < 3; d++) {
            CP16(ring_sm + d * 1024,      (const void*)(Ah + fbase + (ktb + d) * 256));
            CP16(ring_sm + d * 1024 + 16, (const void*)(Al + fbase + (ktb + d) * 256));
            CP_COMMIT();
        }

        auto CONSUME = [&](int k2, uint4 ah, uint4 al) {
            const uint4* wrow = Wfrag + (ktb + k2) * 128 + lane;
            uint4 wf0 = wrow[0];
            uint4 wf1 = wrow[32];
            uint4 wf2 = wrow[64];
            uint4 wf3 = wrow[96];
            mma_bf16(acc_a[0], ah, wf0.x, wf0.y);
            mma_bf16(acc_a[1], ah, wf1.x, wf1.y);
            mma_bf16(acc_a[2], ah, wf2.x, wf2.y);
            mma_bf16(acc_a[3], ah, wf3.x, wf3.y);
            mma_bf16(acc_b[0], al, wf0.x, wf0.y);
            mma_bf16(acc_b[1], al, wf1.x, wf1.y);
            mma_bf16(acc_b[2], al, wf2.x, wf2.y);
            mma_bf16(acc_b[3], al, wf3.x, wf3.y);
            mma_bf16(acc_b[0], ah, wf0.z, wf0.w);
            mma_bf16(acc_b[1], ah, wf1.z, wf1.w);
            mma_bf16(acc_b[2], ah, wf2.z, wf2.w);
            mma_bf16(acc_b[3], ah, wf3.z, wf3.w);
        };

        #pragma unroll 1
        for (int k2 = 0; k2 < 30; k2++) {
            CP_WAIT(2);
            int slot = k2 & 3;
            uint4 ah = ring_rd[slot * 64];
            uint4 al = ring_rd[slot * 64 + 1];
            if (k2 < 29) {
                int tgt = k2 + 3;
                uint32_t d = ring_sm + (tgt & 3) * 1024;
                CP16(d,      (const void*)(Ah + fbase + (ktb + tgt) * 256));
                CP16(d + 16, (const void*)(Al + fbase + (ktb + tgt) * 256));
                CP_COMMIT();
            }
            CONSUME(k2, ah, al);
        }
        {   // k2 = 30
            CP_WAIT(1);
            uint4 ah = ring_rd[(30 & 3) * 64];
            uint4 al = ring_rd[(30 & 3) * 64 + 1];
            CONSUME(30, ah, al);
        }
        {   // k2 = 31
            CP_WAIT(0);
            uint4 ah = ring_rd[(31 & 3) * 64];
            uint4 al = ring_rd[(31 & 3) * 64 + 1];
            CONSUME(31, ah, al);
        }

        // ---- all warps done with ring -> overlay pre, dump partial D ----------
        __syncthreads();
        {
            float* ph = pre + kh * PRE_HALF;
            int r0 = mt * 16 + gid;
            #pragma unroll
            for (int q = 0; q < 4; q++) {
                float2 v0; v0.x = acc_a[q][0] + acc_b[q][0];
                           v0.y = acc_a[q][1] + acc_b[q][1];
                float2 v1; v1.x = acc_a[q][2] + acc_b[q][2];
                           v1.y = acc_a[q][3] + acc_b[q][3];
                *(float2*)&ph[r0 * PRE_STRIDE + q * 8 + 2 * tig]       = v0;
                *(float2*)&ph[(r0 + 8) * PRE_STRIDE + q * 8 + 2 * tig] = v1;
            }
        }
        __syncthreads();

        // ---- fused LSTM + MAGE elementwise (1 item/thread) --------------------
        uint4* AhN = g_Ahi[(t + 1) & 1];
        uint4* AlN = g_Alo[(t + 1) & 1];
        u16* AhN16 = (u16*)AhN;
        u16* AlN16 = (u16*)AlN;

        const int c    = n0 + jj;
        const int ktc  = c >> 4;
        const int ci   = c & 15;
        const int half = ci & 1;
        const int tigc = (ci & 7) >> 1;
        const int regc = ((ci >> 3) & 1) << 1;

        {
            float ph[4], th[4];
            #pragma unroll
            for (int q = 0; q < 4; q++) {
                ph[q] = pre[b * PRE_STRIDE + q * 8 + jj]
                      + pre[PRE_HALF + b * PRE_STRIDE + q * 8 + jj];
                th[q] = pre[(64 + b) * PRE_STRIDE + q * 8 + jj]
                      + pre[PRE_HALF + (64 + b) * PRE_STRIDE + q * 8 + jj];
            }

            float pi = ph[0] + Gr[0];
            float pf = ph[1] + Gr[1];
            float pg = ph[2] + Gr[2];
            float po = ph[3] + Gr[3];

            float n2  = xnv + hnv + 2.0f;
            float nrm = sqrtf(n2);
            float inv = 1.0f / nrm;
            float s   = (n2 - 2.0f) * inv;

            float iv = 1.0f / (1.0f + __expf(-pi));
            float fv = 1.0f / (1.0f + __expf(-pf));
            float gv = __tanhf(pg);
            float ov = 1.0f / (1.0f + __expf(-po));

            float g0 = Pr[0], g1 = Pr[1], g2 = Pr[2], g3 = Pr[3];
            float dpi = g0 * (s + inv) + g1 * inv + th[0];
            float dpf = g1 * s + (g2 + g3) * inv + th[1];
            float dpg = g2 * s + (g0 + g1) * inv + th[2];
            float dpo = g3 * s + (g2 + g3) * inv + th[3];

            float di  = iv * (1.f - iv) * dpi;
            float df  = fv * (1.f - fv) * dpf;
            float dg  = (1.f - gv * gv) * dpg;
            float dov = ov * (1.f - ov) * dpo;

            float c2  = fv * cst + iv * gv;
            float dc2 = df * cst + fv * dcst + di * gv + iv * dg;
            float tc  = __tanhf(c2);
            float h2  = ov * tc;
            float dh2 = dov * tc + ov * (1.f - tc * tc) * dc2;
            cst = c2; dcst = dc2;

            size_t ob = ((size_t)t * BB + b) * HH + c;
            out[ob]       = h2;
            out[OFF + ob] = dh2;

            // scatter into next-step fragment image: h row b, dh row b+64
            {
                int r = b;
                int mtr = r >> 4, ri = r & 15;
                int lane_f = (ri & 7) * 4 + tigc;
                int reg = (ri >> 3) + regc;
                size_t si = ((size_t)(ktc * 8 + mtr) * 32 + lane_f) * 8 + reg * 2 + half;
                u16 hh, hl;
                split_bf(h2, hh, hl);
                AhN16[si] = hh;
                AlN16[si] = hl;
            }
            {
                int r = b + 64;
                int mtr = r >> 4, ri = r & 15;
                int lane_f = (ri & 7) * 4 + tigc;
                int reg = (ri >> 3) + regc;
                size_t si = ((size_t)(ktc * 8 + mtr) * 32 + lane_f) * 8 + reg * 2 + half;
                u16 hh, hl;
                split_bf(dh2, hh, hl);
                AhN16[si] = hh;
                AlN16[si] = hl;
            }

            float sum = h2 * h2;
            #pragma unroll
            for (int o = 1; o < 8; o <<= 1)
                sum += __shfl_xor_sync(0xffffffffu, sum, o);
            if (jj == 0) atomicAdd(&g_hn2[(t + 1) * BB + b], sum);
        }

        // ---- grid barrier ------------------------------------------------------
        __threadfence();
        __syncthreads();
        if (tid == 0) {
            atomicAdd(&g_bar, 1u);
            unsigned tgt = (unsigned)(t + 1) * NCTA;
            unsigned v;
            do {
                asm volatile("ld.acquire.gpu.b32 %0, [%1];"
                             : "=r"(v) : "l"(&g_bar) : "memory");
            } while (v < tgt);
        }
        __syncthreads();
    }
}

// ---------------- launch ------------------------------------------------------
extern "C" void kernel_launch(void* const* d_in, const int* in_sizes, int n_in,
                              void* d_out, int out_size) {
    const float* x   = (const float*)d_in[0];   // [T,B,D]
    const float* g   = (const float*)d_in[1];   // [T,B,4H]
    const float* Wih = (const float*)d_in[2];   // [4H,D]
    const float* Whh = (const float*)d_in[3];   // [4H,H]
    const float* bih = (const float*)d_in[4];   // [4H]
    const float* bhh = (const float*)d_in[5];   // [4H]
    float* out = (float*)d_out;                 // [2,T,B,H]

    cudaFuncSetAttribute(persist_kernel, cudaFuncAttributeMaxDynamicSharedMemorySize,
                         SMEM_TOTAL);
    cudaFuncSetAttribute(pre_gemm_hmma, cudaFuncAttributeMaxDynamicSharedMemorySize,
                         PG_SMEM);

    init_kernel<<<256, 256>>>();
    xnorm_kernel<<<TT * BB, 256>>>(x);
    pre_gemm_hmma<<<dim3(G4 / 128, (TT * BB) / 128), 256, PG_SMEM>>>(x, Wih, bih, bhh);
    persist_kernel<<<NCTA, NTHR, SMEM_TOTAL>>>(g, Whh, out);
}

// round 12
// speedup vs baseline: 1.3302x; 1.3302x over previous
#include <cuda_runtime.h>
#include <cuda_bf16.h>
#include <cstdint>

#define TT 256
#define BB 64
#define DD 1024
#define HH 1024
#define G4 4096
#define EPSF 0.01f
#define NCTA 128
#define NTHR 512

typedef unsigned long long ull;
typedef unsigned short u16;

// ---------------- device scratch -------------------------------------------
static __device__ float g_G[(size_t)TT * BB * G4];   // x@W_ih.T + b_ih + b_hh
static __device__ float g_xn2[TT * BB];              // |x_t|^2
static __device__ float g_hn2[(TT + 1) * BB];        // |h_t|^2 (atomics)
// A-image in mma fragment layout: [parity][kt(64)*mt(8)*lane(32)] uint4
static __device__ uint4 g_Ahi[2][16384];
static __device__ uint4 g_Alo[2][16384];
// progress counters: g_cnt[g] = sum over CTAs in group g of (steps completed)
static __device__ __align__(16) unsigned g_cnt[8];

// ---------------- init (runs every replay) ----------------------------------
__global__ void init_kernel() {
    int idx = blockIdx.x * blockDim.x + threadIdx.x;
    int stride = gridDim.x * blockDim.x;
    uint4 z = make_uint4(0u, 0u, 0u, 0u);
    for (int i = idx; i < 16384; i += stride) {
        g_Ahi[0][i] = z;
        g_Alo[0][i] = z;
    }
    for (int i = idx; i < (TT + 1) * BB; i += stride) g_hn2[i] = 0.f;
    if (idx < 8) g_cnt[idx] = 0u;
}

// ---------------- |x_t|^2 ---------------------------------------------------
__global__ void xnorm_kernel(const float* __restrict__ x) {
    int row = blockIdx.x;
    const float* xr = x + (size_t)row * DD;
    float s = 0.f;
    for (int i = threadIdx.x; i < DD; i += blockDim.x) { float v = xr[i]; s += v * v; }
    __shared__ float red[8];
    #pragma unroll
    for (int o = 16; o > 0; o >>= 1) s += __shfl_xor_sync(0xffffffffu, s, o);
    if ((threadIdx.x & 31) == 0) red[threadIdx.x >> 5] = s;
    __syncthreads();
    if (threadIdx.x < 8) {
        s = red[threadIdx.x];
        #pragma unroll
        for (int o = 4; o > 0; o >>= 1) s += __shfl_xor_sync(0xffu, s, o);
        if (threadIdx.x == 0) g_xn2[row] = s;
    }
}

// ---------------- mma helpers -------------------------------------------------
__device__ __forceinline__ void mma_bf16(float* d, uint4 a, uint32_t b0, uint32_t b1) {
    asm volatile(
        "mma.sync.aligned.m16n8k16.row.col.f32.bf16.bf16.f32 "
        "{%0,%1,%2,%3}, {%4,%5,%6,%7}, {%8,%9}, {%0,%1,%2,%3};"
        : "+f"(d[0]), "+f"(d[1]), "+f"(d[2]), "+f"(d[3])
        : "r"(a.x), "r"(a.y), "r"(a.z), "r"(a.w), "r"(b0), "r"(b1));
}
__device__ __forceinline__ u16 bfu(__nv_bfloat16 b) {
    return __bfloat16_as_ushort(b);
}
__device__ __forceinline__ void split_bf(float v, u16& h, u16& l) {
    __nv_bfloat16 hb = __float2bfloat16(v);
    h = bfu(hb);
    l = bfu(__float2bfloat16(v - __bfloat162float(hb)));
}
// wait until counters[0..3] at cnt4 all reach tgt, then acquire-fence
__device__ __forceinline__ void wait_half(const unsigned* cnt4, unsigned tgt) {
    while (true) {
        unsigned a, bb, c, d;
        asm volatile("ld.volatile.global.v4.u32 {%0,%1,%2,%3}, [%4];"
                     : "=r"(a), "=r"(bb), "=r"(c), "=r"(d) : "l"(cnt4));
        if (a >= tgt && bb >= tgt && c >= tgt && d >= tgt) break;
    }
    asm volatile("fence.acq_rel.gpu;" ::: "memory");
}

// ---------------- HMMA precompute GEMM: G = x @ W_ih.T + (b_ih + b_hh) ------
#define PG_XF_BYTES 32768
#define PG_SMEM     65536

__global__ void __launch_bounds__(256)
pre_gemm_hmma(const float* __restrict__ x, const float* __restrict__ Wih,
              const float* __restrict__ bih, const float* __restrict__ bhh) {
    extern __shared__ __align__(16) char sraw[];
    u16*   xf16 = (u16*)sraw;
    u16*   wf16 = (u16*)(sraw + PG_XF_BYTES);
    uint4* xfv  = (uint4*)sraw;
    uint4* wfv  = (uint4*)(sraw + PG_XF_BYTES);

    const int tid  = threadIdx.x;
    const int w    = tid >> 5;
    const int lane = tid & 31;
    const int gid  = lane >> 2;
    const int tig  = lane & 3;
    const int wm   = w >> 1;
    const int wn   = w & 1;
    const int n0   = blockIdx.x * 128;
    const int m0   = blockIdx.y * 128;
    const int lr   = tid >> 4;
    const int lkp  = tid & 15;

    float acc[2][8][4];
    #pragma unroll
    for (int i = 0; i < 2; i++)
        #pragma unroll
        for (int j = 0; j < 8; j++)
            #pragma unroll
            for (int e = 0; e < 4; e++) acc[i][j][e] = 0.f;

    float2 xs[8], ws[8];
    auto LDG_CHUNK = [&](int k0) {
        #pragma unroll
        for (int i = 0; i < 8; i++) {
            int r = lr + i * 16;
            xs[i] = __ldg((const float2*)(x   + (size_t)(m0 + r) * DD + k0 + lkp * 2));
            ws[i] = __ldg((const float2*)(Wih + (size_t)(n0 + r) * DD + k0 + lkp * 2));
        }
    };
    auto STS_CHUNK = [&](int buf) {
        const int kt   = lkp >> 3;
        const int tigc = lkp & 3;
        const int regk = (lkp >> 2) & 1;
        #pragma unroll
        for (int i = 0; i < 8; i++) {
            int r = lr + i * 16;
            u16 h0, l0, h1, l1;
            split_bf(xs[i].x, h0, l0);
            split_bf(xs[i].y, h1, l1);
            int fi = kt * 8 + (r >> 4);
            int lane_f = (r & 7) * 4 + tigc;
            int reg = ((r >> 3) & 1) + 2 * regk;
            int base = ((buf * 16 + fi) * 32 + lane_f) * 16 + reg * 2;
            *(ushort2*)&xf16[base]     = make_ushort2(h0, h1);
            *(ushort2*)&xf16[base + 8] = make_ushort2(l0, l1);

            split_bf(ws[i].x, h0, l0);
            split_bf(ws[i].y, h1, l1);
            int wi = kt * 16 + (r >> 3);
            int wbase = ((buf * 32 + wi) * 32 + lane_f) * 8 + regk * 2;
            *(ushort2*)&wf16[wbase]     = make_ushort2(h0, h1);
            *(ushort2*)&wf16[wbase + 4] = make_ushort2(l0, l1);
        }
    };

    LDG_CHUNK(0);
    STS_CHUNK(0);
    __syncthreads();

    for (int ch = 0; ch < 32; ch++) {
        const int buf = ch & 1;
        if (ch < 31) LDG_CHUNK((ch + 1) * 32);
        #pragma unroll
        for (int kt = 0; kt < 2; kt++) {
            int fi0 = (buf * 16 + kt * 8 + wm * 2) * 32 + lane;
            uint4 ah0 = xfv[fi0 * 2],        al0 = xfv[fi0 * 2 + 1];
            uint4 ah1 = xfv[(fi0 + 32) * 2], al1 = xfv[(fi0 + 32) * 2 + 1];
            #pragma unroll
            for (int nf = 0; nf < 8; nf++) {
                uint4 wv = wfv[(buf * 32 + kt * 16 + wn * 8 + nf) * 32 + lane];
                mma_bf16(acc[0][nf], ah0, wv.x, wv.y);
                mma_bf16(acc[0][nf], al0, wv.x, wv.y);
                mma_bf16(acc[0][nf], ah0, wv.z, wv.w);
                mma_bf16(acc[1][nf], ah1, wv.x, wv.y);
                mma_bf16(acc[1][nf], al1, wv.x, wv.y);
                mma_bf16(acc[1][nf], ah1, wv.z, wv.w);
            }
        }
        if (ch < 31) {
            __syncthreads();
            STS_CHUNK(buf ^ 1);
            __syncthreads();
        }
    }

    #pragma unroll
    for (int nf = 0; nf < 8; nf++) {
        int col = n0 + wn * 64 + nf * 8 + tig * 2;
        float bs0 = __ldg(&bih[col])     + __ldg(&bhh[col]);
        float bs1 = __ldg(&bih[col + 1]) + __ldg(&bhh[col + 1]);
        #pragma unroll
        for (int im = 0; im < 2; im++) {
            int row = m0 + wm * 32 + im * 16 + gid;
            float2 v0; v0.x = acc[im][nf][0] + bs0; v0.y = acc[im][nf][1] + bs1;
            float2 v1; v1.x = acc[im][nf][2] + bs0; v1.y = acc[im][nf][3] + bs1;
            *(float2*)&g_G[(size_t)row * G4 + col]       = v0;
            *(float2*)&g_G[(size_t)(row + 8) * G4 + col] = v1;
        }
    }
}

// ---------------- persistent HMMA recurrence kernel ---------------------------
// 16 warps; warp = (mt = w&7, kh = w>>3). Split accumulators (8 HMMA chains).
// NO grid barrier: per-step producer/consumer flags. CTA c increments
// g_cnt[c>>4] after its elementwise (release); warp kh waits g_cnt[kh*4..+3]
// >= 16*t before consuming its k-half of step t's A-image (acquire).
#define WFRAG_BYTES (256 * 32 * 16)
#define PRE_STRIDE 34
#define PRE_HALF   (128 * PRE_STRIDE)
#define SMEM_TOTAL (WFRAG_BYTES + 2 * PRE_HALF * 4)

__global__ void __launch_bounds__(NTHR, 1)
persist_kernel(const float* __restrict__ gp, const float* __restrict__ Whh,
               float* __restrict__ out) {
    extern __shared__ __align__(16) char sraw[];
    uint4* Wfrag = (uint4*)sraw;
    float* pre   = (float*)(sraw + WFRAG_BYTES);

    const int tid  = threadIdx.x;
    const int w    = tid >> 5;
    const int lane = tid & 31;
    const int mt   = w & 7;
    const int kh   = w >> 3;
    const int gid  = lane >> 2;
    const int tig  = lane & 3;
    const int n0   = blockIdx.x * 8;
    const int jj   = tid & 7;
    const int b    = tid >> 3;           // 0..63 (tid < 512)
    const int my_grp = blockIdx.x >> 4;

    // ---- one-time: build W fragments (hi/lo) into SMEM ----------------------
    #pragma unroll 1
    for (int idx = w; idx < 256; idx += 16) {
        int q = idx & 3, kt = idx >> 2;
        const float* wr = Whh + (size_t)(q * HH + n0 + gid) * HH + kt * 16 + tig * 2;
        float v00 = __ldg(wr), v01 = __ldg(wr + 1);
        float v10 = __ldg(wr + 8), v11 = __ldg(wr + 9);
        u16 h00, l00, h01, l01, h10, l10, h11, l11;
        split_bf(v00, h00, l00); split_bf(v01, h01, l01);
        split_bf(v10, h10, l10); split_bf(v11, h11, l11);
        Wfrag[idx * 32 + lane] = make_uint4(
            (uint32_t)h00 | ((uint32_t)h01 << 16),
            (uint32_t)h10 | ((uint32_t)h11 << 16),
            (uint32_t)l00 | ((uint32_t)l01 << 16),
            (uint32_t)l10 | ((uint32_t)l11 << 16));
    }
    __syncthreads();

    float cst = 0.f, dcst = 0.f;
    const size_t OFF = (size_t)TT * BB * HH;

    for (int t = 0; t < TT; t++) {
        // ---- prefetch static elementwise operands (NOT hn2) ------------------
        float Gr[4], Pr[4], xnv;
        {
            size_t gb = ((size_t)t * BB + b) * G4 + n0 + jj;
            #pragma unroll
            for (int q = 0; q < 4; q++) {
                Gr[q] = __ldg(&g_G[gb + q * HH]);
                Pr[q] = EPSF * __ldg(&gp[gb + q * HH]);
            }
            xnv = __ldg(&g_xn2[t * BB + b]);
        }

        // ---- data-flow wait: this warp's k-half of A[t] is published ---------
        wait_half(&g_cnt[kh * 4], (unsigned)t * 16u);

        // ---- HMMA mainloop with split accumulators ---------------------------
        float acc_a[4][4], acc_b[4][4];
        #pragma unroll
        for (int q = 0; q < 4; q++)
            #pragma unroll
            for (int e = 0; e < 4; e++) { acc_a[q][e] = 0.f; acc_b[q][e] = 0.f; }

        const uint4* Ah = g_Ahi[t & 1];
        const uint4* Al = g_Alo[t & 1];
        const int ktb   = kh * 32;
        const int fbase = mt * 32 + lane;

        uint4 hA = __ldcg(Ah + fbase + ktb * 256);
        uint4 lA = __ldcg(Al + fbase + ktb * 256);
        uint4 hB = __ldcg(Ah + fbase + (ktb + 1) * 256);
        uint4 lB = __ldcg(Al + fbase + (ktb + 1) * 256);

        #pragma unroll 1
        for (int k2 = 0; k2 < 32; k2++) {
            uint4 ah = hA, al = lA;
            hA = hB; lA = lB;
            if (k2 < 30) {
                hB = __ldcg(Ah + fbase + (ktb + k2 + 2) * 256);
                lB = __ldcg(Al + fbase + (ktb + k2 + 2) * 256);
            }
            const uint4* wrow = Wfrag + (ktb + k2) * 128 + lane;
            uint4 wf0 = wrow[0];
            uint4 wf1 = wrow[32];
            uint4 wf2 = wrow[64];
            uint4 wf3 = wrow[96];
            mma_bf16(acc_a[0], ah, wf0.x, wf0.y);
            mma_bf16(acc_a[1], ah, wf1.x, wf1.y);
            mma_bf16(acc_a[2], ah, wf2.x, wf2.y);
            mma_bf16(acc_a[3], ah, wf3.x, wf3.y);
            mma_bf16(acc_b[0], al, wf0.x, wf0.y);
            mma_bf16(acc_b[1], al, wf1.x, wf1.y);
            mma_bf16(acc_b[2], al, wf2.x, wf2.y);
            mma_bf16(acc_b[3], al, wf3.x, wf3.y);
            mma_bf16(acc_b[0], ah, wf0.z, wf0.w);
            mma_bf16(acc_b[1], ah, wf1.z, wf1.w);
            mma_bf16(acc_b[2], ah, wf2.z, wf2.w);
            mma_bf16(acc_b[3], ah, wf3.z, wf3.w);
        }

        // ---- dump partial D (a+b) to pre[kh] -----------------------------------
        {
            float* ph = pre + kh * PRE_HALF;
            int r0 = mt * 16 + gid;
            #pragma unroll
            for (int q = 0; q < 4; q++) {
                float2 v0; v0.x = acc_a[q][0] + acc_b[q][0];
                           v0.y = acc_a[q][1] + acc_b[q][1];
                float2 v1; v1.x = acc_a[q][2] + acc_b[q][2];
                           v1.y = acc_a[q][3] + acc_b[q][3];
                *(float2*)&ph[r0 * PRE_STRIDE + q * 8 + 2 * tig]       = v0;
                *(float2*)&ph[(r0 + 8) * PRE_STRIDE + q * 8 + 2 * tig] = v1;
            }
        }
        __syncthreads();

        // hn2[t] is complete: mainloop finished => all CTAs did elementwise t-1
        float hnv = __ldcg(&g_hn2[t * BB + b]);

        // ---- fused LSTM + MAGE elementwise (1 item/thread) --------------------
        uint4* AhN = g_Ahi[(t + 1) & 1];
        uint4* AlN = g_Alo[(t + 1) & 1];
        u16* AhN16 = (u16*)AhN;
        u16* AlN16 = (u16*)AlN;

        const int c    = n0 + jj;
        const int ktc  = c >> 4;
        const int ci   = c & 15;
        const int half = ci & 1;
        const int tigc = (ci & 7) >> 1;
        const int regc = ((ci >> 3) & 1) << 1;

        {
            float ph[4], th[4];
            #pragma unroll
            for (int q = 0; q < 4; q++) {
                ph[q] = pre[b * PRE_STRIDE + q * 8 + jj]
                      + pre[PRE_HALF + b * PRE_STRIDE + q * 8 + jj];
                th[q] = pre[(64 + b) * PRE_STRIDE + q * 8 + jj]
                      + pre[PRE_HALF + (64 + b) * PRE_STRIDE + q * 8 + jj];
            }

            float pi = ph[0] + Gr[0];
            float pf = ph[1] + Gr[1];
            float pg = ph[2] + Gr[2];
            float po = ph[3] + Gr[3];

            float n2  = xnv + hnv + 2.0f;
            float nrm = sqrtf(n2);
            float inv = 1.0f / nrm;
            float s   = (n2 - 2.0f) * inv;

            float iv = 1.0f / (1.0f + __expf(-pi));
            float fv = 1.0f / (1.0f + __expf(-pf));
            float gv = __tanhf(pg);
            float ov = 1.0f / (1.0f + __expf(-po));

            float g0 = Pr[0], g1 = Pr[1], g2 = Pr[2], g3 = Pr[3];
            float dpi = g0 * (s + inv) + g1 * inv + th[0];
            float dpf = g1 * s + (g2 + g3) * inv + th[1];
            float dpg = g2 * s + (g0 + g1) * inv + th[2];
            float dpo = g3 * s + (g2 + g3) * inv + th[3];

            float di  = iv * (1.f - iv) * dpi;
            float df  = fv * (1.f - fv) * dpf;
            float dg  = (1.f - gv * gv) * dpg;
            float dov = ov * (1.f - ov) * dpo;

            float c2  = fv * cst + iv * gv;
            float dc2 = df * cst + fv * dcst + di * gv + iv * dg;
            float tc  = __tanhf(c2);
            float h2  = ov * tc;
            float dh2 = dov * tc + ov * (1.f - tc * tc) * dc2;
            cst = c2; dcst = dc2;

            size_t ob = ((size_t)t * BB + b) * HH + c;
            out[ob]       = h2;
            out[OFF + ob] = dh2;

            // scatter into next-step fragment image: h row b, dh row b+64
            {
                int r = b;
                int mtr = r >> 4, ri = r & 15;
                int lane_f = (ri & 7) * 4 + tigc;
                int reg = (ri >> 3) + regc;
                size_t si = ((size_t)(ktc * 8 + mtr) * 32 + lane_f) * 8 + reg * 2 + half;
                u16 hh, hl;
                split_bf(h2, hh, hl);
                AhN16[si] = hh;
                AlN16[si] = hl;
            }
            {
                int r = b + 64;
                int mtr = r >> 4, ri = r & 15;
                int lane_f = (ri & 7) * 4 + tigc;
                int reg = (ri >> 3) + regc;
                size_t si = ((size_t)(ktc * 8 + mtr) * 32 + lane_f) * 8 + reg * 2 + half;
                u16 hh, hl;
                split_bf(dh2, hh, hl);
                AhN16[si] = hh;
                AlN16[si] = hl;
            }

            float sum = h2 * h2;
            #pragma unroll
            for (int o = 1; o < 8; o <<= 1)
                sum += __shfl_xor_sync(0xffffffffu, sum, o);
            if (jj == 0) atomicAdd(&g_hn2[(t + 1) * BB + b], sum);
        }

        // ---- publish: A[t+1] columns + hn2[t+1] contribution written ----------
        __threadfence();
        __syncthreads();
        if (tid == 0) atomicAdd(&g_cnt[my_grp], 1u);
    }
}

// ---------------- launch ------------------------------------------------------
extern "C" void kernel_launch(void* const* d_in, const int* in_sizes, int n_in,
                              void* d_out, int out_size) {
    const float* x   = (const float*)d_in[0];   // [T,B,D]
    const float* g   = (const float*)d_in[1];   // [T,B,4H]
    const float* Wih = (const float*)d_in[2];   // [4H,D]
    const float* Whh = (const float*)d_in[3];   // [4H,H]
    const float* bih = (const float*)d_in[4];   // [4H]
    const float* bhh = (const float*)d_in[5];   // [4H]
    float* out = (float*)d_out;                 // [2,T,B,H]

    cudaFuncSetAttribute(persist_kernel, cudaFuncAttributeMaxDynamicSharedMemorySize,
                         SMEM_TOTAL);
    cudaFuncSetAttribute(pre_gemm_hmma, cudaFuncAttributeMaxDynamicSharedMemorySize,
                         PG_SMEM);

    init_kernel<<<256, 256>>>();
    xnorm_kernel<<<TT * BB, 256>>>(x);
    pre_gemm_hmma<<<dim3(G4 / 128, (TT * BB) / 128), 256, PG_SMEM>>>(x, Wih, bih, bhh);
    persist_kernel<<<NCTA, NTHR, SMEM_TOTAL>>>(g, Whh, out);
}

// round 13
// speedup vs baseline: 1.6310x; 1.2261x over previous
#include <cuda_runtime.h>
#include <cuda_bf16.h>
#include <cstdint>

#define TT 256
#define BB 64
#define DD 1024
#define HH 1024
#define G4 4096
#define EPSF 0.01f
#define NCTA 128
#define NTHR 512

typedef unsigned long long ull;
typedef unsigned short u16;

// ---------------- device scratch -------------------------------------------
static __device__ float g_G[(size_t)TT * BB * G4];   // x@W_ih.T + b_ih + b_hh
static __device__ float g_xn2[TT * BB];              // |x_t|^2
static __device__ float g_hn2[(TT + 1) * BB];        // |h_t|^2 (atomics)
// A-image in mma fragment layout: [parity][kt(64)*mt(8)*lane(32)] uint4
static __device__ uint4 g_Ahi[2][16384];
static __device__ uint4 g_Alo[2][16384];
static __device__ unsigned g_bar;                    // global step barrier

// ---------------- init (runs every replay) ----------------------------------
__global__ void init_kernel() {
    int idx = blockIdx.x * blockDim.x + threadIdx.x;
    int stride = gridDim.x * blockDim.x;
    uint4 z = make_uint4(0u, 0u, 0u, 0u);
    for (int i = idx; i < 16384; i += stride) {
        g_Ahi[0][i] = z;
        g_Alo[0][i] = z;
    }
    for (int i = idx; i < (TT + 1) * BB; i += stride) g_hn2[i] = 0.f;
    if (idx == 0) g_bar = 0u;
}

// ---------------- |x_t|^2 ---------------------------------------------------
__global__ void xnorm_kernel(const float* __restrict__ x) {
    int row = blockIdx.x;
    const float* xr = x + (size_t)row * DD;
    float s = 0.f;
    for (int i = threadIdx.x; i < DD; i += blockDim.x) { float v = xr[i]; s += v * v; }
    __shared__ float red[8];
    #pragma unroll
    for (int o = 16; o > 0; o >>= 1) s += __shfl_xor_sync(0xffffffffu, s, o);
    if ((threadIdx.x & 31) == 0) red[threadIdx.x >> 5] = s;
    __syncthreads();
    if (threadIdx.x < 8) {
        s = red[threadIdx.x];
        #pragma unroll
        for (int o = 4; o > 0; o >>= 1) s += __shfl_xor_sync(0xffu, s, o);
        if (threadIdx.x == 0) g_xn2[row] = s;
    }
}

// ---------------- mma helpers -------------------------------------------------
__device__ __forceinline__ void mma_bf16(float* d, uint4 a, uint32_t b0, uint32_t b1) {
    asm volatile(
        "mma.sync.aligned.m16n8k16.row.col.f32.bf16.bf16.f32 "
        "{%0,%1,%2,%3}, {%4,%5,%6,%7}, {%8,%9}, {%0,%1,%2,%3};"
        : "+f"(d[0]), "+f"(d[1]), "+f"(d[2]), "+f"(d[3])
        : "r"(a.x), "r"(a.y), "r"(a.z), "r"(a.w), "r"(b0), "r"(b1));
}
__device__ __forceinline__ u16 bfu(__nv_bfloat16 b) {
    return __bfloat16_as_ushort(b);
}
__device__ __forceinline__ void split_bf(float v, u16& h, u16& l) {
    __nv_bfloat16 hb = __float2bfloat16(v);
    h = bfu(hb);
    l = bfu(__float2bfloat16(v - __bfloat162float(hb)));
}

// ---------------- HMMA precompute GEMM: G = x @ W_ih.T + (b_ih + b_hh) ------
#define PG_XF_BYTES 32768
#define PG_SMEM     65536

__global__ void __launch_bounds__(256)
pre_gemm_hmma(const float* __restrict__ x, const float* __restrict__ Wih,
              const float* __restrict__ bih, const float* __restrict__ bhh) {
    extern __shared__ __align__(16) char sraw[];
    u16*   xf16 = (u16*)sraw;
    u16*   wf16 = (u16*)(sraw + PG_XF_BYTES);
    uint4* xfv  = (uint4*)sraw;
    uint4* wfv  = (uint4*)(sraw + PG_XF_BYTES);

    const int tid  = threadIdx.x;
    const int w    = tid >> 5;
    const int lane = tid & 31;
    const int gid  = lane >> 2;
    const int tig  = lane & 3;
    const int wm   = w >> 1;
    const int wn   = w & 1;
    const int n0   = blockIdx.x * 128;
    const int m0   = blockIdx.y * 128;
    const int lr   = tid >> 4;
    const int lkp  = tid & 15;

    float acc[2][8][4];
    #pragma unroll
    for (int i = 0; i < 2; i++)
        #pragma unroll
        for (int j = 0; j < 8; j++)
            #pragma unroll
            for (int e = 0; e < 4; e++) acc[i][j][e] = 0.f;

    float2 xs[8], ws[8];
    auto LDG_CHUNK = [&](int k0) {
        #pragma unroll
        for (int i = 0; i < 8; i++) {
            int r = lr + i * 16;
            xs[i] = __ldg((const float2*)(x   + (size_t)(m0 + r) * DD + k0 + lkp * 2));
            ws[i] = __ldg((const float2*)(Wih + (size_t)(n0 + r) * DD + k0 + lkp * 2));
        }
    };
    auto STS_CHUNK = [&](int buf) {
        const int kt   = lkp >> 3;
        const int tigc = lkp & 3;
        const int regk = (lkp >> 2) & 1;
        #pragma unroll
        for (int i = 0; i < 8; i++) {
            int r = lr + i * 16;
            u16 h0, l0, h1, l1;
            split_bf(xs[i].x, h0, l0);
            split_bf(xs[i].y, h1, l1);
            int fi = kt * 8 + (r >> 4);
            int lane_f = (r & 7) * 4 + tigc;
            int reg = ((r >> 3) & 1) + 2 * regk;
            int base = ((buf * 16 + fi) * 32 + lane_f) * 16 + reg * 2;
            *(ushort2*)&xf16[base]     = make_ushort2(h0, h1);
            *(ushort2*)&xf16[base + 8] = make_ushort2(l0, l1);

            split_bf(ws[i].x, h0, l0);
            split_bf(ws[i].y, h1, l1);
            int wi = kt * 16 + (r >> 3);
            int wbase = ((buf * 32 + wi) * 32 + lane_f) * 8 + regk * 2;
            *(ushort2*)&wf16[wbase]     = make_ushort2(h0, h1);
            *(ushort2*)&wf16[wbase + 4] = make_ushort2(l0, l1);
        }
    };

    LDG_CHUNK(0);
    STS_CHUNK(0);
    __syncthreads();

    for (int ch = 0; ch < 32; ch++) {
        const int buf = ch & 1;
        if (ch < 31) LDG_CHUNK((ch + 1) * 32);
        #pragma unroll
        for (int kt = 0; kt < 2; kt++) {
            int fi0 = (buf * 16 + kt * 8 + wm * 2) * 32 + lane;
            uint4 ah0 = xfv[fi0 * 2],        al0 = xfv[fi0 * 2 + 1];
            uint4 ah1 = xfv[(fi0 + 32) * 2], al1 = xfv[(fi0 + 32) * 2 + 1];
            #pragma unroll
            for (int nf = 0; nf < 8; nf++) {
                uint4 wv = wfv[(buf * 32 + kt * 16 + wn * 8 + nf) * 32 + lane];
                mma_bf16(acc[0][nf], ah0, wv.x, wv.y);
                mma_bf16(acc[0][nf], al0, wv.x, wv.y);
                mma_bf16(acc[0][nf], ah0, wv.z, wv.w);
                mma_bf16(acc[1][nf], ah1, wv.x, wv.y);
                mma_bf16(acc[1][nf], al1, wv.x, wv.y);
                mma_bf16(acc[1][nf], ah1, wv.z, wv.w);
            }
        }
        if (ch < 31) {
            __syncthreads();
            STS_CHUNK(buf ^ 1);
            __syncthreads();
        }
    }

    #pragma unroll
    for (int nf = 0; nf < 8; nf++) {
        int col = n0 + wn * 64 + nf * 8 + tig * 2;
        float bs0 = __ldg(&bih[col])     + __ldg(&bhh[col]);
        float bs1 = __ldg(&bih[col + 1]) + __ldg(&bhh[col + 1]);
        #pragma unroll
        for (int im = 0; im < 2; im++) {
            int row = m0 + wm * 32 + im * 16 + gid;
            float2 v0; v0.x = acc[im][nf][0] + bs0; v0.y = acc[im][nf][1] + bs1;
            float2 v1; v1.x = acc[im][nf][2] + bs0; v1.y = acc[im][nf][3] + bs1;
            *(float2*)&g_G[(size_t)row * G4 + col]       = v0;
            *(float2*)&g_G[(size_t)(row + 8) * G4 + col] = v1;
        }
    }
}

// ---------------- persistent HMMA recurrence kernel ---------------------------
// 16 warps; warp = (mt = w&7, kh = w>>3). Merged accumulators (4 q-chains,
// depth 3) + DEPTH-4 A-image register ring: LDG coverage ~4 k2-periods
// (~400-500 cyc) > L2 latency (234/262) -> long-scoreboard stalls gone.
// SMEM: Wfrag uint4[64 kt][4 q][32 lane] = 128KB; pre float[2 kh][128][34].
#define WFRAG_BYTES (256 * 32 * 16)
#define PRE_STRIDE 34
#define PRE_HALF   (128 * PRE_STRIDE)
#define SMEM_TOTAL (WFRAG_BYTES + 2 * PRE_HALF * 4)

__global__ void __launch_bounds__(NTHR, 1)
persist_kernel(const float* __restrict__ gp, const float* __restrict__ Whh,
               float* __restrict__ out) {
    extern __shared__ __align__(16) char sraw[];
    uint4* Wfrag = (uint4*)sraw;
    float* pre   = (float*)(sraw + WFRAG_BYTES);

    const int tid  = threadIdx.x;
    const int w    = tid >> 5;
    const int lane = tid & 31;
    const int mt   = w & 7;
    const int kh   = w >> 3;
    const int gid  = lane >> 2;
    const int tig  = lane & 3;
    const int n0   = blockIdx.x * 8;
    const int jj   = tid & 7;
    const int b    = tid >> 3;           // 0..63 (tid < 512)

    // ---- one-time: build W fragments (hi/lo) into SMEM ----------------------
    #pragma unroll 1
    for (int idx = w; idx < 256; idx += 16) {
        int q = idx & 3, kt = idx >> 2;
        const float* wr = Whh + (size_t)(q * HH + n0 + gid) * HH + kt * 16 + tig * 2;
        float v00 = __ldg(wr), v01 = __ldg(wr + 1);
        float v10 = __ldg(wr + 8), v11 = __ldg(wr + 9);
        u16 h00, l00, h01, l01, h10, l10, h11, l11;
        split_bf(v00, h00, l00); split_bf(v01, h01, l01);
        split_bf(v10, h10, l10); split_bf(v11, h11, l11);
        Wfrag[idx * 32 + lane] = make_uint4(
            (uint32_t)h00 | ((uint32_t)h01 << 16),
            (uint32_t)h10 | ((uint32_t)h11 << 16),
            (uint32_t)l00 | ((uint32_t)l01 << 16),
            (uint32_t)l10 | ((uint32_t)l11 << 16));
    }
    __syncthreads();

    float cst = 0.f, dcst = 0.f;
    const size_t OFF = (size_t)TT * BB * HH;

    for (int t = 0; t < TT; t++) {
        // ---- prefetch elementwise operands ----------------------------------
        float Gr[4], Pr[4], xnv, hnv;
        {
            size_t gb = ((size_t)t * BB + b) * G4 + n0 + jj;
            #pragma unroll
            for (int q = 0; q < 4; q++) {
                Gr[q] = __ldg(&g_G[gb + q * HH]);
                Pr[q] = EPSF * __ldg(&gp[gb + q * HH]);
            }
            xnv = __ldg(&g_xn2[t * BB + b]);
            hnv = __ldcg(&g_hn2[t * BB + b]);
        }

        // ---- HMMA mainloop: merged acc + depth-4 A register ring -------------
        float acc[4][4];
        #pragma unroll
        for (int q = 0; q < 4; q++)
            #pragma unroll
            for (int e = 0; e < 4; e++) acc[q][e] = 0.f;

        const uint4* Ah = g_Ahi[t & 1];
        const uint4* Al = g_Alo[t & 1];
        const int ktb   = kh * 32;
        const int fbase = mt * 32 + lane;

        uint4 rh[4], rl[4];
        #pragma unroll
        for (int d = 0; d < 4; d++) {
            rh[d] = __ldcg(Ah + fbase + (ktb + d) * 256);
            rl[d] = __ldcg(Al + fbase + (ktb + d) * 256);
        }

        #pragma unroll 1
        for (int ko = 0; ko < 32; ko += 4) {
            #pragma unroll
            for (int u = 0; u < 4; u++) {
                const int k2 = ko + u;
                uint4 ah = rh[u], al = rl[u];
                if (k2 < 28) {
                    rh[u] = __ldcg(Ah + fbase + (ktb + k2 + 4) * 256);
                    rl[u] = __ldcg(Al + fbase + (ktb + k2 + 4) * 256);
                }
                const uint4* wrow = Wfrag + (ktb + k2) * 128 + lane;
                uint4 wf0 = wrow[0];
                uint4 wf1 = wrow[32];
                uint4 wf2 = wrow[64];
                uint4 wf3 = wrow[96];
                // pass 1: Ah * Whi (4 independent chains)
                mma_bf16(acc[0], ah, wf0.x, wf0.y);
                mma_bf16(acc[1], ah, wf1.x, wf1.y);
                mma_bf16(acc[2], ah, wf2.x, wf2.y);
                mma_bf16(acc[3], ah, wf3.x, wf3.y);
                // pass 2: Al * Whi
                mma_bf16(acc[0], al, wf0.x, wf0.y);
                mma_bf16(acc[1], al, wf1.x, wf1.y);
                mma_bf16(acc[2], al, wf2.x, wf2.y);
                mma_bf16(acc[3], al, wf3.x, wf3.y);
                // pass 3: Ah * Wlo
                mma_bf16(acc[0], ah, wf0.z, wf0.w);
                mma_bf16(acc[1], ah, wf1.z, wf1.w);
                mma_bf16(acc[2], ah, wf2.z, wf2.w);
                mma_bf16(acc[3], ah, wf3.z, wf3.w);
            }
        }

        // ---- dump partial D to pre[kh] ----------------------------------------
        {
            float* ph = pre + kh * PRE_HALF;
            int r0 = mt * 16 + gid;
            #pragma unroll
            for (int q = 0; q < 4; q++) {
                float2 v0; v0.x = acc[q][0]; v0.y = acc[q][1];
                float2 v1; v1.x = acc[q][2]; v1.y = acc[q][3];
                *(float2*)&ph[r0 * PRE_STRIDE + q * 8 + 2 * tig]       = v0;
                *(float2*)&ph[(r0 + 8) * PRE_STRIDE + q * 8 + 2 * tig] = v1;
            }
        }
        __syncthreads();

        // ---- fused LSTM + MAGE elementwise (1 item/thread) --------------------
        uint4* AhN = g_Ahi[(t + 1) & 1];
        uint4* AlN = g_Alo[(t + 1) & 1];
        u16* AhN16 = (u16*)AhN;
        u16* AlN16 = (u16*)AlN;

        const int c    = n0 + jj;
        const int ktc  = c >> 4;
        const int ci   = c & 15;
        const int half = ci & 1;
        const int tigc = (ci & 7) >> 1;
        const int regc = ((ci >> 3) & 1) << 1;

        {
            float ph[4], th[4];
            #pragma unroll
            for (int q = 0; q < 4; q++) {
                ph[q] = pre[b * PRE_STRIDE + q * 8 + jj]
                      + pre[PRE_HALF + b * PRE_STRIDE + q * 8 + jj];
                th[q] = pre[(64 + b) * PRE_STRIDE + q * 8 + jj]
                      + pre[PRE_HALF + (64 + b) * PRE_STRIDE + q * 8 + jj];
            }

            float pi = ph[0] + Gr[0];
            float pf = ph[1] + Gr[1];
            float pg = ph[2] + Gr[2];
            float po = ph[3] + Gr[3];

            float n2  = xnv + hnv + 2.0f;
            float nrm = sqrtf(n2);
            float inv = 1.0f / nrm;
            float s   = (n2 - 2.0f) * inv;

            float iv = 1.0f / (1.0f + __expf(-pi));
            float fv = 1.0f / (1.0f + __expf(-pf));
            float gv = __tanhf(pg);
            float ov = 1.0f / (1.0f + __expf(-po));

            float g0 = Pr[0], g1 = Pr[1], g2 = Pr[2], g3 = Pr[3];
            float dpi = g0 * (s + inv) + g1 * inv + th[0];
            float dpf = g1 * s + (g2 + g3) * inv + th[1];
            float dpg = g2 * s + (g0 + g1) * inv + th[2];
            float dpo = g3 * s + (g2 + g3) * inv + th[3];

            float di  = iv * (1.f - iv) * dpi;
            float df  = fv * (1.f - fv) * dpf;
            float dg  = (1.f - gv * gv) * dpg;
            float dov = ov * (1.f - ov) * dpo;

            float c2  = fv * cst + iv * gv;
            float dc2 = df * cst + fv * dcst + di * gv + iv * dg;
            float tc  = __tanhf(c2);
            float h2  = ov * tc;
            float dh2 = dov * tc + ov * (1.f - tc * tc) * dc2;
            cst = c2; dcst = dc2;

            size_t ob = ((size_t)t * BB + b) * HH + c;
            out[ob]       = h2;
            out[OFF + ob] = dh2;

            // scatter into next-step fragment image: h row b, dh row b+64
            {
                int r = b;
                int mtr = r >> 4, ri = r & 15;
                int lane_f = (ri & 7) * 4 + tigc;
                int reg = (ri >> 3) + regc;
                size_t si = ((size_t)(ktc * 8 + mtr) * 32 + lane_f) * 8 + reg * 2 + half;
                u16 hh, hl;
                split_bf(h2, hh, hl);
                AhN16[si] = hh;
                AlN16[si] = hl;
            }
            {
                int r = b + 64;
                int mtr = r >> 4, ri = r & 15;
                int lane_f = (ri & 7) * 4 + tigc;
                int reg = (ri >> 3) + regc;
                size_t si = ((size_t)(ktc * 8 + mtr) * 32 + lane_f) * 8 + reg * 2 + half;
                u16 hh, hl;
                split_bf(dh2, hh, hl);
                AhN16[si] = hh;
                AlN16[si] = hl;
            }

            float sum = h2 * h2;
            #pragma unroll
            for (int o = 1; o < 8; o <<= 1)
                sum += __shfl_xor_sync(0xffffffffu, sum, o);
            if (jj == 0) atomicAdd(&g_hn2[(t + 1) * BB + b], sum);
        }

        // ---- grid barrier ------------------------------------------------------
        __threadfence();
        __syncthreads();
        if (tid == 0) {
            atomicAdd(&g_bar, 1u);
            unsigned tgt = (unsigned)(t + 1) * NCTA;
            unsigned v;
            do {
                asm volatile("ld.acquire.gpu.b32 %0, [%1];"
                             : "=r"(v) : "l"(&g_bar) : "memory");
            } while (v < tgt);
        }
        __syncthreads();
    }
}

// ---------------- launch ------------------------------------------------------
extern "C" void kernel_launch(void* const* d_in, const int* in_sizes, int n_in,
                              void* d_out, int out_size) {
    const float* x   = (const float*)d_in[0];   // [T,B,D]
    const float* g   = (const float*)d_in[1];   // [T,B,4H]
    const float* Wih = (const float*)d_in[2];   // [4H,D]
    const float* Whh = (const float*)d_in[3];   // [4H,H]
    const float* bih = (const float*)d_in[4];   // [4H]
    const float* bhh = (const float*)d_in[5];   // [4H]
    float* out = (float*)d_out;                 // [2,T,B,H]

    cudaFuncSetAttribute(persist_kernel, cudaFuncAttributeMaxDynamicSharedMemorySize,
                         SMEM_TOTAL);
    cudaFuncSetAttribute(pre_gemm_hmma, cudaFuncAttributeMaxDynamicSharedMemorySize,
                         PG_SMEM);

    init_kernel<<<256, 256>>>();
    xnorm_kernel<<<TT * BB, 256>>>(x);
    pre_gemm_hmma<<<dim3(G4 / 128, (TT * BB) / 128), 256, PG_SMEM>>>(x, Wih, bih, bhh);
    persist_kernel<<<NCTA, NTHR, SMEM_TOTAL>>>(g, Whh, out);
}

// round 14
// speedup vs baseline: 1.8550x; 1.1374x over previous
#include <cuda_runtime.h>
#include <cuda_bf16.h>
#include <cstdint>

#define TT 256
#define BB 64
#define DD 1024
#define HH 1024
#define G4 4096
#define EPSF 0.01f
#define NCTA 128
#define NTHR 512

typedef unsigned long long ull;
typedef unsigned short u16;

// ---------------- device scratch -------------------------------------------
static __device__ float g_G[(size_t)TT * BB * G4];   // x@W_ih.T + b_ih + b_hh
static __device__ float g_xn2[TT * BB];              // |x_t|^2
static __device__ float g_hn2[(TT + 1) * BB];        // |h_t|^2 (atomics)
// A-image in mma fragment layout: [parity][kt(64)*mt(8)*lane(32)] uint4
static __device__ uint4 g_Ahi[2][16384];
static __device__ uint4 g_Alo[2][16384];
// packed fragment images for pre_gemm (bf16 hi/lo, SMEM-layout-identical)
static __device__ uint4 g_xpack[(size_t)128 * 64 * 512];  // [mb][kt][mt][lane][2]
static __device__ uint4 g_wpack[(size_t)32 * 64 * 512];   // [nb][kt][wq][lane]
static __device__ unsigned g_bar;                    // global step barrier

// ---------------- init (runs every replay) ----------------------------------
__global__ void init_kernel() {
    int idx = blockIdx.x * blockDim.x + threadIdx.x;
    int stride = gridDim.x * blockDim.x;
    uint4 z = make_uint4(0u, 0u, 0u, 0u);
    for (int i = idx; i < 16384; i += stride) {
        g_Ahi[0][i] = z;
        g_Alo[0][i] = z;
    }
    for (int i = idx; i < (TT + 1) * BB; i += stride) g_hn2[i] = 0.f;
    if (idx == 0) g_bar = 0u;
}

// ---------------- |x_t|^2 ---------------------------------------------------
__global__ void xnorm_kernel(const float* __restrict__ x) {
    int row = blockIdx.x;
    const float* xr = x + (size_t)row * DD;
    float s = 0.f;
    for (int i = threadIdx.x; i < DD; i += blockDim.x) { float v = xr[i]; s += v * v; }
    __shared__ float red[8];
    #pragma unroll
    for (int o = 16; o > 0; o >>= 1) s += __shfl_xor_sync(0xffffffffu, s, o);
    if ((threadIdx.x & 31) == 0) red[threadIdx.x >> 5] = s;
    __syncthreads();
    if (threadIdx.x < 8) {
        s = red[threadIdx.x];
        #pragma unroll
        for (int o = 4; o > 0; o >>= 1) s += __shfl_xor_sync(0xffu, s, o);
        if (threadIdx.x == 0) g_xn2[row] = s;
    }
}

// ---------------- helpers -----------------------------------------------------
__device__ __forceinline__ void mma_bf16(float* d, uint4 a, uint32_t b0, uint32_t b1) {
    asm volatile(
        "mma.sync.aligned.m16n8k16.row.col.f32.bf16.bf16.f32 "
        "{%0,%1,%2,%3}, {%4,%5,%6,%7}, {%8,%9}, {%0,%1,%2,%3};"
        : "+f"(d[0]), "+f"(d[1]), "+f"(d[2]), "+f"(d[3])
        : "r"(a.x), "r"(a.y), "r"(a.z), "r"(a.w), "r"(b0), "r"(b1));
}
__device__ __forceinline__ u16 bfu(__nv_bfloat16 b) {
    return __bfloat16_as_ushort(b);
}
__device__ __forceinline__ void split_bf(float v, u16& h, u16& l) {
    __nv_bfloat16 hb = __float2bfloat16(v);
    h = bfu(hb);
    l = bfu(__float2bfloat16(v - __bfloat162float(hb)));
}

// ---------------- prepack: x -> fragment image (bf16 hi/lo) -------------------
// mapping identical to the old STS_CHUNK (A-side).
__global__ void prepack_x(const float* __restrict__ x) {
    const int row = blockIdx.x;          // 0..16383
    const int kq  = threadIdx.x;         // float4 index 0..255
    float4 v = __ldg((const float4*)(x + (size_t)row * DD) + kq);
    const int mb = row >> 7, r = row & 127, mt = r >> 4;
    u16* dst = (u16*)g_xpack;
    #pragma unroll
    for (int p = 0; p < 2; p++) {
        int kp = kq * 2 + p;
        int kt = kp >> 3, tigc = kp & 3, regk = (kp >> 2) & 1;
        int lane_f = (r & 7) * 4 + tigc;
        int reg = ((r >> 3) & 1) + 2 * regk;
        float v0 = p ? v.z : v.x, v1 = p ? v.w : v.y;
        u16 h0, l0, h1, l1;
        split_bf(v0, h0, l0); split_bf(v1, h1, l1);
        size_t base = ((((size_t)mb * 64 + kt) * 8 + mt) * 32 + lane_f) * 16 + reg * 2;
        *(ushort2*)&dst[base]     = make_ushort2(h0, h1);
        *(ushort2*)&dst[base + 8] = make_ushort2(l0, l1);
    }
}

// ---------------- prepack: W_ih -> fragment image (bf16 hi/lo) ----------------
// mapping identical to the old STS_CHUNK (B-side).
__global__ void prepack_w(const float* __restrict__ Wih) {
    const int row = blockIdx.x;          // n-row 0..4095
    const int kq  = threadIdx.x;
    float4 v = __ldg((const float4*)(Wih + (size_t)row * DD) + kq);
    const int nb = row >> 7, r = row & 127, wq = r >> 3;
    u16* dst = (u16*)g_wpack;
    #pragma unroll
    for (int p = 0; p < 2; p++) {
        int kp = kq * 2 + p;
        int kt = kp >> 3, tigc = kp & 3, regk = (kp >> 2) & 1;
        int lane_f = (r & 7) * 4 + tigc;
        float v0 = p ? v.z : v.x, v1 = p ? v.w : v.y;
        u16 h0, l0, h1, l1;
        split_bf(v0, h0, l0); split_bf(v1, h1, l1);
        size_t base = ((((size_t)nb * 64 + kt) * 16 + wq) * 32 + lane_f) * 8 + regk * 2;
        *(ushort2*)&dst[base]     = make_ushort2(h0, h1);
        *(ushort2*)&dst[base + 4] = make_ushort2(l0, l1);
    }
}

// ---------------- HMMA precompute GEMM: G = x @ W_ih.T + (b_ih + b_hh) ------
// Loader = flat 16KB copies from pre-packed images; single sync per chunk.
#define PG_SMEM (4096 * 16)     // 2 buf x 1024 uint4 (x) + 2 buf x 1024 uint4 (w)

__global__ void __launch_bounds__(256)
pre_gemm_hmma(const float* __restrict__ bih, const float* __restrict__ bhh) {
    extern __shared__ __align__(16) uint4 sv[];
    uint4* xv = sv;          // [buf][1024]
    uint4* wv = sv + 2048;   // [buf][1024]

    const int tid  = threadIdx.x;
    const int w    = tid >> 5;
    const int lane = tid & 31;
    const int gid  = lane >> 2;
    const int tig  = lane & 3;
    const int wm   = w >> 1;
    const int wn   = w & 1;
    const int nb   = blockIdx.x;      // 0..31
    const int mb   = blockIdx.y;      // 0..127
    const int n0   = nb * 128;
    const int m0   = mb * 128;

    const uint4* xg = g_xpack + (size_t)mb * 64 * 512;
    const uint4* wg = g_wpack + (size_t)nb * 64 * 512;

    float acc[2][8][4];
    #pragma unroll
    for (int i = 0; i < 2; i++)
        #pragma unroll
        for (int j = 0; j < 8; j++)
            #pragma unroll
            for (int e = 0; e < 4; e++) acc[i][j][e] = 0.f;

    uint4 st[8];
    auto LDGC = [&](int ch) {
        const uint4* xs = xg + (size_t)ch * 1024;
        const uint4* ws = wg + (size_t)ch * 1024;
        #pragma unroll
        for (int i = 0; i < 4; i++) st[i]     = __ldg(xs + tid + i * 256);
        #pragma unroll
        for (int i = 0; i < 4; i++) st[4 + i] = __ldg(ws + tid + i * 256);
    };
    auto STSC = [&](int buf) {
        #pragma unroll
        for (int i = 0; i < 4; i++) xv[buf * 1024 + tid + i * 256] = st[i];
        #pragma unroll
        for (int i = 0; i < 4; i++) wv[buf * 1024 + tid + i * 256] = st[4 + i];
    };

    LDGC(0);
    STSC(0);
    __syncthreads();

    for (int ch = 0; ch < 32; ch++) {
        const int buf = ch & 1;
        if (ch < 31) LDGC(ch + 1);
        #pragma unroll
        for (int kt = 0; kt < 2; kt++) {
            int fi0 = buf * 1024 + ((kt * 8 + wm * 2) * 32 + lane) * 2;
            uint4 ah0 = xv[fi0],      al0 = xv[fi0 + 1];
            uint4 ah1 = xv[fi0 + 64], al1 = xv[fi0 + 65];
            #pragma unroll
            for (int nf = 0; nf < 8; nf++) {
                uint4 wvv = wv[buf * 1024 + (kt * 16 + wn * 8 + nf) * 32 + lane];
                mma_bf16(acc[0][nf], ah0, wvv.x, wvv.y);
                mma_bf16(acc[0][nf], al0, wvv.x, wvv.y);
                mma_bf16(acc[0][nf], ah0, wvv.z, wvv.w);
                mma_bf16(acc[1][nf], ah1, wvv.x, wvv.y);
                mma_bf16(acc[1][nf], al1, wvv.x, wvv.y);
                mma_bf16(acc[1][nf], ah1, wvv.z, wvv.w);
            }
        }
        if (ch < 31) {
            STSC(buf ^ 1);
            __syncthreads();
        }
    }

    #pragma unroll
    for (int nf = 0; nf < 8; nf++) {
        int col = n0 + wn * 64 + nf * 8 + tig * 2;
        float bs0 = __ldg(&bih[col])     + __ldg(&bhh[col]);
        float bs1 = __ldg(&bih[col + 1]) + __ldg(&bhh[col + 1]);
        #pragma unroll
        for (int im = 0; im < 2; im++) {
            int row = m0 + wm * 32 + im * 16 + gid;
            float2 v0; v0.x = acc[im][nf][0] + bs0; v0.y = acc[im][nf][1] + bs1;
            float2 v1; v1.x = acc[im][nf][2] + bs0; v1.y = acc[im][nf][3] + bs1;
            *(float2*)&g_G[(size_t)row * G4 + col]       = v0;
            *(float2*)&g_G[(size_t)(row + 8) * G4 + col] = v1;
        }
    }
}

// ---------------- persistent HMMA recurrence kernel ---------------------------
// (R13 winner, unchanged except: barrier arrive moved before the out[] stores)
#define WFRAG_BYTES (256 * 32 * 16)
#define PRE_STRIDE 34
#define PRE_HALF   (128 * PRE_STRIDE)
#define SMEM_TOTAL (WFRAG_BYTES + 2 * PRE_HALF * 4)

__global__ void __launch_bounds__(NTHR, 1)
persist_kernel(const float* __restrict__ gp, const float* __restrict__ Whh,
               float* __restrict__ out) {
    extern __shared__ __align__(16) char sraw[];
    uint4* Wfrag = (uint4*)sraw;
    float* pre   = (float*)(sraw + WFRAG_BYTES);

    const int tid  = threadIdx.x;
    const int w    = tid >> 5;
    const int lane = tid & 31;
    const int mt   = w & 7;
    const int kh   = w >> 3;
    const int gid  = lane >> 2;
    const int tig  = lane & 3;
    const int n0   = blockIdx.x * 8;
    const int jj   = tid & 7;
    const int b    = tid >> 3;           // 0..63 (tid < 512)

    // ---- one-time: build W fragments (hi/lo) into SMEM ----------------------
    #pragma unroll 1
    for (int idx = w; idx < 256; idx += 16) {
        int q = idx & 3, kt = idx >> 2;
        const float* wr = Whh + (size_t)(q * HH + n0 + gid) * HH + kt * 16 + tig * 2;
        float v00 = __ldg(wr), v01 = __ldg(wr + 1);
        float v10 = __ldg(wr + 8), v11 = __ldg(wr + 9);
        u16 h00, l00, h01, l01, h10, l10, h11, l11;
        split_bf(v00, h00, l00); split_bf(v01, h01, l01);
        split_bf(v10, h10, l10); split_bf(v11, h11, l11);
        Wfrag[idx * 32 + lane] = make_uint4(
            (uint32_t)h00 | ((uint32_t)h01 << 16),
            (uint32_t)h10 | ((uint32_t)h11 << 16),
            (uint32_t)l00 | ((uint32_t)l01 << 16),
            (uint32_t)l10 | ((uint32_t)l11 << 16));
    }
    __syncthreads();

    float cst = 0.f, dcst = 0.f;
    const size_t OFF = (size_t)TT * BB * HH;

    for (int t = 0; t < TT; t++) {
        // ---- prefetch elementwise operands ----------------------------------
        float Gr[4], Pr[4], xnv, hnv;
        {
            size_t gb = ((size_t)t * BB + b) * G4 + n0 + jj;
            #pragma unroll
            for (int q = 0; q < 4; q++) {
                Gr[q] = __ldg(&g_G[gb + q * HH]);
                Pr[q] = EPSF * __ldg(&gp[gb + q * HH]);
            }
            xnv = __ldg(&g_xn2[t * BB + b]);
            hnv = __ldcg(&g_hn2[t * BB + b]);
        }

        // ---- HMMA mainloop: merged acc + depth-4 A register ring -------------
        float acc[4][4];
        #pragma unroll
        for (int q = 0; q < 4; q++)
            #pragma unroll
            for (int e = 0; e < 4; e++) acc[q][e] = 0.f;

        const uint4* Ah = g_Ahi[t & 1];
        const uint4* Al = g_Alo[t & 1];
        const int ktb   = kh * 32;
        const int fbase = mt * 32 + lane;

        uint4 rh[4], rl[4];
        #pragma unroll
        for (int d = 0; d < 4; d++) {
            rh[d] = __ldcg(Ah + fbase + (ktb + d) * 256);
            rl[d] = __ldcg(Al + fbase + (ktb + d) * 256);
        }

        #pragma unroll 1
        for (int ko = 0; ko < 32; ko += 4) {
            #pragma unroll
            for (int u = 0; u < 4; u++) {
                const int k2 = ko + u;
                uint4 ah = rh[u], al = rl[u];
                if (k2 < 28) {
                    rh[u] = __ldcg(Ah + fbase + (ktb + k2 + 4) * 256);
                    rl[u] = __ldcg(Al + fbase + (ktb + k2 + 4) * 256);
                }
                const uint4* wrow = Wfrag + (ktb + k2) * 128 + lane;
                uint4 wf0 = wrow[0];
                uint4 wf1 = wrow[32];
                uint4 wf2 = wrow[64];
                uint4 wf3 = wrow[96];
                mma_bf16(acc[0], ah, wf0.x, wf0.y);
                mma_bf16(acc[1], ah, wf1.x, wf1.y);
                mma_bf16(acc[2], ah, wf2.x, wf2.y);
                mma_bf16(acc[3], ah, wf3.x, wf3.y);
                mma_bf16(acc[0], al, wf0.x, wf0.y);
                mma_bf16(acc[1], al, wf1.x, wf1.y);
                mma_bf16(acc[2], al, wf2.x, wf2.y);
                mma_bf16(acc[3], al, wf3.x, wf3.y);
                mma_bf16(acc[0], ah, wf0.z, wf0.w);
                mma_bf16(acc[1], ah, wf1.z, wf1.w);
                mma_bf16(acc[2], ah, wf2.z, wf2.w);
                mma_bf16(acc[3], ah, wf3.z, wf3.w);
            }
        }

        // ---- dump partial D to pre[kh] ----------------------------------------
        {
            float* ph = pre + kh * PRE_HALF;
            int r0 = mt * 16 + gid;
            #pragma unroll
            for (int q = 0; q < 4; q++) {
                float2 v0; v0.x = acc[q][0]; v0.y = acc[q][1];
                float2 v1; v1.x = acc[q][2]; v1.y = acc[q][3];
                *(float2*)&ph[r0 * PRE_STRIDE + q * 8 + 2 * tig]       = v0;
                *(float2*)&ph[(r0 + 8) * PRE_STRIDE + q * 8 + 2 * tig] = v1;
            }
        }
        __syncthreads();

        // ---- fused LSTM + MAGE elementwise (1 item/thread) --------------------
        uint4* AhN = g_Ahi[(t + 1) & 1];
        uint4* AlN = g_Alo[(t + 1) & 1];
        u16* AhN16 = (u16*)AhN;
        u16* AlN16 = (u16*)AlN;

        const int c    = n0 + jj;
        const int ktc  = c >> 4;
        const int ci   = c & 15;
        const int half = ci & 1;
        const int tigc = (ci & 7) >> 1;
        const int regc = ((ci >> 3) & 1) << 1;

        float h2, dh2;
        size_t ob;
        {
            float ph[4], th[4];
            #pragma unroll
            for (int q = 0; q < 4; q++) {
                ph[q] = pre[b * PRE_STRIDE + q * 8 + jj]
                      + pre[PRE_HALF + b * PRE_STRIDE + q * 8 + jj];
                th[q] = pre[(64 + b) * PRE_STRIDE + q * 8 + jj]
                      + pre[PRE_HALF + (64 + b) * PRE_STRIDE + q * 8 + jj];
            }

            float pi = ph[0] + Gr[0];
            float pf = ph[1] + Gr[1];
            float pg = ph[2] + Gr[2];
            float po = ph[3] + Gr[3];

            float n2  = xnv + hnv + 2.0f;
            float nrm = sqrtf(n2);
            float inv = 1.0f / nrm;
            float s   = (n2 - 2.0f) * inv;

            float iv = 1.0f / (1.0f + __expf(-pi));
            float fv = 1.0f / (1.0f + __expf(-pf));
            float gv = __tanhf(pg);
            float ov = 1.0f / (1.0f + __expf(-po));

            float g0 = Pr[0], g1 = Pr[1], g2 = Pr[2], g3 = Pr[3];
            float dpi = g0 * (s + inv) + g1 * inv + th[0];
            float dpf = g1 * s + (g2 + g3) * inv + th[1];
            float dpg = g2 * s + (g0 + g1) * inv + th[2];
            float dpo = g3 * s + (g2 + g3) * inv + th[3];

            float di  = iv * (1.f - iv) * dpi;
            float df  = fv * (1.f - fv) * dpf;
            float dg  = (1.f - gv * gv) * dpg;
            float dov = ov * (1.f - ov) * dpo;

            float c2  = fv * cst + iv * gv;
            float dc2 = df * cst + fv * dcst + di * gv + iv * dg;
            float tc  = __tanhf(c2);
            h2  = ov * tc;
            dh2 = dov * tc + ov * (1.f - tc * tc) * dc2;
            cst = c2; dcst = dc2;

            ob = ((size_t)t * BB + b) * HH + c;

            // scatter into next-step fragment image: h row b, dh row b+64
            {
                int r = b;
                int mtr = r >> 4, ri = r & 15;
                int lane_f = (ri & 7) * 4 + tigc;
                int reg = (ri >> 3) + regc;
                size_t si = ((size_t)(ktc * 8 + mtr) * 32 + lane_f) * 8 + reg * 2 + half;
                u16 hh, hl;
                split_bf(h2, hh, hl);
                AhN16[si] = hh;
                AlN16[si] = hl;
            }
            {
                int r = b + 64;
                int mtr = r >> 4, ri = r & 15;
                int lane_f = (ri & 7) * 4 + tigc;
                int reg = (ri >> 3) + regc;
                size_t si = ((size_t)(ktc * 8 + mtr) * 32 + lane_f) * 8 + reg * 2 + half;
                u16 hh, hl;
                split_bf(dh2, hh, hl);
                AhN16[si] = hh;
                AlN16[si] = hl;
            }

            float sum = h2 * h2;
            #pragma unroll
            for (int o = 1; o < 8; o <<= 1)
                sum += __shfl_xor_sync(0xffffffffu, sum, o);
            if (jj == 0) atomicAdd(&g_hn2[(t + 1) * BB + b], sum);
        }

        // ---- barrier: arrive early, overlap out[] stores with the poll ---------
        __threadfence();
        __syncthreads();
        if (tid == 0) atomicAdd(&g_bar, 1u);
        out[ob]       = h2;          // unordered outputs, hidden under the poll
        out[OFF + ob] = dh2;
        if (tid == 0) {
            unsigned tgt = (unsigned)(t + 1) * NCTA;
            unsigned v;
            do {
                asm volatile("ld.acquire.gpu.b32 %0, [%1];"
                             : "=r"(v) : "l"(&g_bar) : "memory");
            } while (v < tgt);
        }
        __syncthreads();
    }
}

// ---------------- launch ------------------------------------------------------
extern "C" void kernel_launch(void* const* d_in, const int* in_sizes, int n_in,
                              void* d_out, int out_size) {
    const float* x   = (const float*)d_in[0];   // [T,B,D]
    const float* g   = (const float*)d_in[1];   // [T,B,4H]
    const float* Wih = (const float*)d_in[2];   // [4H,D]
    const float* Whh = (const float*)d_in[3];   // [4H,H]
    const float* bih = (const float*)d_in[4];   // [4H]
    const float* bhh = (const float*)d_in[5];   // [4H]
    float* out = (float*)d_out;                 // [2,T,B,H]

    cudaFuncSetAttribute(persist_kernel, cudaFuncAttributeMaxDynamicSharedMemorySize,
                         SMEM_TOTAL);
    cudaFuncSetAttribute(pre_gemm_hmma, cudaFuncAttributeMaxDynamicSharedMemorySize,
                         PG_SMEM);

    init_kernel<<<256, 256>>>();
    xnorm_kernel<<<TT * BB, 256>>>(x);
    prepack_x<<<TT * BB, 256>>>(x);
    prepack_w<<<G4, 256>>>(Wih);
    pre_gemm_hmma<<<dim3(32, 128), 256, PG_SMEM>>>(bih, bhh);
    persist_kernel<<<NCTA, NTHR, SMEM_TOTAL>>>(g, Whh, out);
}